// round 7
// baseline (speedup 1.0000x reference)
#include <cuda_runtime.h>
#include <cstdint>
#include <cstddef>

#define BB 32
#define TT 128
#define LL 64
#define HH 512
#define AA 256
#define DD 512
#define NCOL 2048
#define UCOLS 2304
#define NBLK 144
#define NTH 512
#define QCH 128

typedef unsigned long long u64;

// ---------------- device scratch ----------------
__device__ float g_xg[(size_t)TT * BB * NCOL];     // [t*32+b][col]
__device__ float g_ctr[(size_t)BB * LL * AA];      // ctx_trans [b*64+l][a]
__device__ float g_ctxC[(size_t)BB * LL * NCOL];   // context@C [b*64+l][col]
__device__ float g_Wpk[(size_t)256 * UCOLS * 2];   // [k2][c]{keven,kodd}
__device__ float g_gbuf[(size_t)BB * NCOL];        // [b][col]
__device__ float g_attv[(size_t)BB * AA];          // [b][a]
__device__ float g_hp[(size_t)256 * BB * 2];       // h pairs [k2][b]{e,o}
__device__ float g_cst[(size_t)BB * HH];           // c state [b][ch]
__device__ float g_zbias[512];
__device__ unsigned g_arr[NBLK * 32];
__device__ unsigned g_rel;
__device__ unsigned g_epoch;

// ---------------- helpers ----------------
__device__ __forceinline__ u64 pk2(float lo, float hi) {
    u64 r; asm("mov.b64 %0, {%1,%2};" : "=l"(r) : "f"(lo), "f"(hi)); return r;
}
__device__ __forceinline__ float2 upk2(u64 v) {
    float2 r; asm("mov.b64 {%0,%1}, %2;" : "=f"(r.x), "=f"(r.y) : "l"(v)); return r;
}
__device__ __forceinline__ u64 fma2(u64 a, u64 b, u64 c) {
    u64 d; asm("fma.rn.f32x2 %0, %1, %2, %3;" : "=l"(d) : "l"(a), "l"(b), "l"(c)); return d;
}
__device__ __forceinline__ u64 add2(u64 a, u64 b) {
    u64 d; asm("add.rn.f32x2 %0, %1, %2;" : "=l"(d) : "l"(a), "l"(b)); return d;
}
__device__ __forceinline__ float tanh_ap(float x) {
    float y; asm("tanh.approx.f32 %0, %1;" : "=f"(y) : "f"(x)); return y;
}
__device__ __forceinline__ float sig_ap(float x) {
    return fmaf(tanh_ap(0.5f * x), 0.5f, 0.5f);
}

__device__ __forceinline__ void gbar(int bid, int tid, unsigned gen) {
    __syncthreads();
    if (tid == 0) {
        __threadfence();
        *(volatile unsigned*)&g_arr[bid * 32] = gen;
    }
    if (bid == 0) {
        if (tid < NBLK) {
            while (*(volatile unsigned*)&g_arr[tid * 32] < gen) { }
        }
        __syncthreads();
        if (tid == 0) {
            __threadfence();
            *(volatile unsigned*)&g_rel = gen;
        }
    }
    if (tid == 0) {
        while (*(volatile unsigned*)&g_rel < gen) { }
        __threadfence();
    }
    __syncthreads();
}

// ---------------- prologue GEMM, f32x2 inner product ----------------
__global__ void __launch_bounds__(256) gemm_proj(
    const float* __restrict__ A,
    const float* __restrict__ Wa, const float* __restrict__ Wb,
    const float* __restrict__ Wc, const float* __restrict__ Wd,
    const float* __restrict__ ba, const float* __restrict__ bbi,
    const float* __restrict__ bc, const float* __restrict__ bd,
    float* __restrict__ Out, int Ncols, int wN, int wstride, int tb_mode)
{
    __shared__ u64 As2[8][64];
    __shared__ u64 Bs2[8][64];
    int tid = threadIdx.x;
    int ntile = blockIdx.x, mtile = blockIdx.y;

    int gate = (ntile * 64) / 512;
    const float* Wsel = (gate == 0) ? Wa : (gate == 1) ? Wb : (gate == 2) ? Wc : Wd;
    const float* bsel = (gate == 0) ? ba : (gate == 1) ? bbi : (gate == 2) ? bc : bd;
    int ncolbase = (ntile * 64) % wN;

    int a_r = tid >> 2;
    int a_k = (tid & 3) * 4;
    int grow = mtile * 64 + a_r;
    const float* aptr;
    if (tb_mode) {
        int t = grow >> 5, b = grow & 31;
        aptr = A + ((size_t)(b * TT + t)) * DD;
    } else {
        aptr = A + (size_t)grow * DD;
    }
    int bl_k2 = (tid >> 4) & 7;
    int bl_n  = (tid & 15) * 4;
    bool bldr = tid < 128;

    int tx = tid & 15, ty = tid >> 4;
    u64 acc2[4][4];
#pragma unroll
    for (int i = 0; i < 4; i++)
#pragma unroll
        for (int j = 0; j < 4; j++) acc2[i][j] = 0;

    for (int k0 = 0; k0 < DD; k0 += 16) {
        float4 av = *(const float4*)(aptr + k0 + a_k);
        float4 b0, b1;
        if (bldr) {
            b0 = *(const float4*)(Wsel + (size_t)(k0 + 2 * bl_k2) * wstride + ncolbase + bl_n);
            b1 = *(const float4*)(Wsel + (size_t)(k0 + 2 * bl_k2 + 1) * wstride + ncolbase + bl_n);
        }
        __syncthreads();
        As2[(a_k >> 1)][a_r]     = pk2(av.x, av.y);
        As2[(a_k >> 1) + 1][a_r] = pk2(av.z, av.w);
        if (bldr) {
            Bs2[bl_k2][bl_n + 0] = pk2(b0.x, b1.x);
            Bs2[bl_k2][bl_n + 1] = pk2(b0.y, b1.y);
            Bs2[bl_k2][bl_n + 2] = pk2(b0.z, b1.z);
            Bs2[bl_k2][bl_n + 3] = pk2(b0.w, b1.w);
        }
        __syncthreads();
#pragma unroll
        for (int k2 = 0; k2 < 8; k2++) {
            ulonglong2 a01 = *(const ulonglong2*)&As2[k2][ty * 4];
            ulonglong2 a23 = *(const ulonglong2*)&As2[k2][ty * 4 + 2];
            ulonglong2 b01 = *(const ulonglong2*)&Bs2[k2][tx * 4];
            ulonglong2 b23 = *(const ulonglong2*)&Bs2[k2][tx * 4 + 2];
            u64 aa[4] = {a01.x, a01.y, a23.x, a23.y};
            u64 bb4[4] = {b01.x, b01.y, b23.x, b23.y};
#pragma unroll
            for (int i = 0; i < 4; i++)
#pragma unroll
                for (int j = 0; j < 4; j++) acc2[i][j] = fma2(aa[i], bb4[j], acc2[i][j]);
        }
    }
#pragma unroll
    for (int i = 0; i < 4; i++) {
        int gr = mtile * 64 + ty * 4 + i;
        float r[4];
#pragma unroll
        for (int j = 0; j < 4; j++) {
            float2 v = upk2(acc2[i][j]);
            r[j] = v.x + v.y + bsel[(ncolbase + tx * 4 + j) % wN];
        }
        if (tb_mode) {
            int t = gr >> 5, b = gr & 31;
            size_t cb = (size_t)t * Ncols + ntile * 64 + tx * 4;
            // store [t*32+b][col] row-major like mode 0 path but rows reordered
            (void)cb;
            *(float4*)(Out + ((size_t)(t * 32 + b)) * Ncols + ntile * 64 + tx * 4) =
                make_float4(r[0], r[1], r[2], r[3]);
        } else {
            *(float4*)(Out + (size_t)gr * Ncols + ntile * 64 + tx * 4) =
                make_float4(r[0], r[1], r[2], r[3]);
        }
    }
}

// smem map (floats)
#define OFF_RED   16384
#define OFF_ATT   (16384 + 4096)
#define OFF_W2    (OFF_ATT + 256)
#define OFF_E     (OFF_W2 + 256)
#define OFF_A     (OFF_E + 64)
#define OFF_APAIR (OFF_A + 64)
#define OFF_G     (OFF_APAIR + 128)
#define OFF_SUM   (OFF_G + 512)
#define SMEM_FLOATS (OFF_SUM + 8)

// ---------------- persistent recurrent kernel ----------------
__global__ void __launch_bounds__(NTH, 1) recur_kernel(
    const float* __restrict__ context,
    const float* __restrict__ mask,
    const int*   __restrict__ cmask,
    const float* __restrict__ U0, const float* __restrict__ U1,
    const float* __restrict__ U2, const float* __restrict__ U3,
    const float* __restrict__ W1h,
    const float* __restrict__ W2, const float* __restrict__ b2,
    float* __restrict__ out)
{
    extern __shared__ float smem[];
    float* sTp   = smem;
    float* sRed  = smem + OFF_RED;
    float* sAtt  = smem + OFF_ATT;
    float* sW2s  = smem + OFF_W2;
    float* sE    = smem + OFF_E;
    float* sA    = smem + OFF_A;
    u64*   sApr  = (u64*)(smem + OFF_APAIR);
    float* sG    = smem + OFF_G;
    float* sSum  = smem + OFF_SUM;
    u64*   sTp64 = (u64*)sTp;
    u64*   sRedU = (u64*)(sRed + 1536);   // 256 u64, disjoint from out_x partials [0..1023]

    const int tid = threadIdx.x;
    const int bid = blockIdx.x;
    float* out_h = out;
    float* out_c = out + (size_t)BB * TT * HH;
    float* out_x = out + (size_t)2 * BB * TT * HH;
    const float b2v = b2[0];

    unsigned base = *(volatile unsigned*)&g_epoch;

    // ---- prologue A: cooperative weight repack (U gates + W1h → g_Wpk) ----
    for (int i = bid * NTH + tid; i < 256 * UCOLS; i += NBLK * NTH) {
        int k2 = i / UCOLS;
        int c = i - k2 * UCOLS;
        float e, o;
        if (c < 2048) {
            int g = c >> 9, ch = c & 511;
            const float* Ug = (g == 0) ? U0 : (g == 1) ? U1 : (g == 2) ? U2 : U3;
            e = Ug[(size_t)(2 * k2) * 512 + ch];
            o = Ug[(size_t)(2 * k2 + 1) * 512 + ch];
        } else {
            int a = c - 2048;
            e = W1h[(size_t)(2 * k2) * AA + a];
            o = W1h[(size_t)(2 * k2 + 1) * AA + a];
        }
        g_Wpk[(size_t)i * 2 + 0] = e;
        g_Wpk[(size_t)i * 2 + 1] = o;
    }

    // P1 roles
    const int c0 = bid * 16;
    const int cp = tid & 7;
    const int bq = (tid >> 3) & 7;
    const int kq = tid >> 6;           // 0..7
    const int c  = c0 + cp * 2;

    // P2 roles
    const bool p2act = (bid < 128);
    const int pb = bid >> 2;
    const int pq = bid & 3;
    const int chp = tid & 255;         // local col-pair (512 local cols)
    const int lh  = tid >> 8;          // l-half

    // ---- prologue B: register-resident ctxC slice for P2 ----
    u64 rv[32];
    {
        int lc0 = chp * 2;
        int gg = lc0 >> 7, ii = lc0 & 127;
        int gcol = gg * 512 + pq * QCH + ii;
        const float* cc = g_ctxC + ((size_t)(pb * 64 + lh * 32)) * NCOL + gcol;
        if (p2act) {
#pragma unroll
            for (int li = 0; li < 32; li++)
                rv[li] = *(const u64*)(cc + (size_t)li * NCOL);
        } else {
#pragma unroll
            for (int li = 0; li < 32; li++) rv[li] = 0;
        }
    }
    if (tid < AA) sW2s[tid] = W2[tid];

    for (int t = 0; t < TT; t++) {
        // ================= PHASE 1: unified GEMM over h =================
        if (t > 0) {
            const float4* src = (const float4*)g_hp;
            for (int f4 = tid; f4 < 4096; f4 += NTH)
                *(float4*)&sTp[f4 * 4] = src[f4];
        }
        __syncthreads();

        u64 ac[2][4];
#pragma unroll
        for (int i = 0; i < 2; i++)
#pragma unroll
            for (int j = 0; j < 4; j++) ac[i][j] = 0;
        if (t > 0) {
            const u64* wp = (const u64*)g_Wpk + (size_t)(kq * 32) * UCOLS + c;
            const u64* hp = sTp64 + (kq * 32) * 32 + bq * 4;
#pragma unroll 4
            for (int p = 0; p < 32; p++) {
                ulonglong2 w2 = *(const ulonglong2*)wp;
                ulonglong2 ha = *(const ulonglong2*)hp;
                ulonglong2 hb = *(const ulonglong2*)(hp + 2);
                ac[0][0] = fma2(w2.x, ha.x, ac[0][0]);
                ac[0][1] = fma2(w2.x, ha.y, ac[0][1]);
                ac[0][2] = fma2(w2.x, hb.x, ac[0][2]);
                ac[0][3] = fma2(w2.x, hb.y, ac[0][3]);
                ac[1][0] = fma2(w2.y, ha.x, ac[1][0]);
                ac[1][1] = fma2(w2.y, ha.y, ac[1][1]);
                ac[1][2] = fma2(w2.y, hb.x, ac[1][2]);
                ac[1][3] = fma2(w2.y, hb.y, ac[1][3]);
                wp += UCOLS; hp += 32;
            }
        }
#pragma unroll
        for (int bi = 0; bi < 4; bi++) {
            float2 r0 = upk2(ac[0][bi]);
            float2 r1 = upk2(ac[1][bi]);
            *(float2*)&sRed[kq * 512 + (bq * 4 + bi) * 16 + cp * 2] =
                make_float2(r0.x + r0.y, r1.x + r1.y);
        }
        __syncthreads();
        {
            int o = tid;   // 512 outputs, 1 per thread
            float s = 0.f;
#pragma unroll
            for (int q = 0; q < 8; q++) s += sRed[q * 512 + o];
            int b = o >> 4, colL = o & 15;
            if (bid < 128) {
                int col = c0 + colL;
                s += g_xg[((size_t)t * BB + b) * NCOL + col];
                g_gbuf[(size_t)b * NCOL + col] = s;
            } else {
                g_attv[b * AA + (c0 - 2048) + colL] = s;
            }
        }
        gbar(bid, tid, base + (unsigned)(2 * t + 1));

        // ================= PHASE 2: per (b, quarter) block =================
        if (p2act) {
            const int b = pb;
            if (tid < AA) sAtt[tid] = g_attv[b * AA + tid];
            __syncthreads();
            // scores: warp per 4 l
            {
                int warp = tid >> 5, lane = tid & 31;
#pragma unroll
                for (int i = 0; i < 4; i++) {
                    int l = warp * 4 + i;
                    const float* ct = g_ctr + ((size_t)b * LL + l) * AA;
                    float p = 0.f;
#pragma unroll
                    for (int j = 0; j < 8; j++) {
                        int a = lane + j * 32;
                        p += tanh_ap(ct[a] + sAtt[a]) * sW2s[a];
                    }
#pragma unroll
                    for (int o = 16; o > 0; o >>= 1) p += __shfl_xor_sync(0xffffffffu, p, o);
                    if (lane == 0)
                        sE[l] = __expf(p + b2v) * (float)cmask[b * LL + l];
                }
            }
            __syncthreads();
            if (tid < 32) {
                float v = sE[tid] + sE[tid + 32];
#pragma unroll
                for (int o = 16; o > 0; o >>= 1) v += __shfl_xor_sync(0xffffffffu, v, o);
                if (tid == 0) sSum[0] = v;
            }
            __syncthreads();
            if (tid < 64) {
                float av = sE[tid] * __fdividef(1.0f, sSum[0]);
                sA[tid] = av;
                sApr[tid] = pk2(av, av);
            }
            __syncthreads();

            // gsum from registers (32 fma2) + out_x partials, both before one sync
            u64 acc = 0;
#pragma unroll
            for (int li = 0; li < 32; li++)
                acc = fma2(rv[li], sApr[lh * 32 + li], acc);
            if (lh == 1) sRedU[chp] = acc;

            if (tid < 256) {
                int lg = tid >> 5, d4 = tid & 31;   // 8 l-groups x 32 float4
                float4 xp = make_float4(0.f, 0.f, 0.f, 0.f);
                const float* cb = context + ((size_t)b * LL + lg * 8) * DD + pq * QCH + d4 * 4;
#pragma unroll
                for (int li = 0; li < 8; li++) {
                    float av = sA[lg * 8 + li];
                    float4 v = *(const float4*)(cb + (size_t)li * DD);
                    xp.x += av * v.x; xp.y += av * v.y; xp.z += av * v.z; xp.w += av * v.w;
                }
                *(float4*)&sRed[tid * 4] = xp;
            }
            __syncthreads();
            if (lh == 0) {
                u64 tot = add2(acc, sRedU[chp]);
                *(u64*)&sG[chp * 2] = tot;
            }
            if (tid < 32) {
                float4 s = make_float4(0.f, 0.f, 0.f, 0.f);
#pragma unroll
                for (int lg = 0; lg < 8; lg++) {
                    float4 v = *(const float4*)&sRed[(lg * 32 + tid) * 4];
                    s.x += v.x; s.y += v.y; s.z += v.z; s.w += v.w;
                }
                *(float4*)(out_x + ((size_t)b * TT + t) * DD + pq * QCH + tid * 4) = s;
            }
            __syncthreads();

            // fused LSTM epilogue: 64 ch-pairs
            if (tid < 64) {
                int i2 = tid;
                int ch0 = pq * QCH + i2 * 2;
                float gs[4][2];
#pragma unroll
                for (int g = 0; g < 4; g++) {
                    float2 sg = *(const float2*)&sG[(g * 64 + i2) * 2];
                    float2 gb = *(const float2*)&g_gbuf[(size_t)b * NCOL + g * 512 + ch0];
                    gs[g][0] = sg.x + gb.x;
                    gs[g][1] = sg.y + gb.y;
                }
                float2 cprev = make_float2(0.f, 0.f), hprev = make_float2(0.f, 0.f);
                if (t > 0) {
                    cprev = *(const float2*)&g_cst[(size_t)b * HH + ch0];
                    hprev = *(const float2*)&g_hp[(size_t)(ch0 >> 1) * 64 + b * 2];
                }
                float m = mask[b * TT + t];
                float hn[2], cn[2];
#pragma unroll
                for (int pp = 0; pp < 2; pp++) {
                    float iv = sig_ap(gs[0][pp]);
                    float fv = sig_ap(gs[1][pp]);
                    float gv = tanh_ap(gs[2][pp]);
                    float ov = sig_ap(gs[3][pp]);
                    float cp_ = pp ? cprev.y : cprev.x;
                    float hp_ = pp ? hprev.y : hprev.x;
                    float cnew = fv * cp_ + iv * gv;
                    float hnew = ov * tanh_ap(cnew);
                    hn[pp] = (1.f - m) * hp_ + m * hnew;
                    cn[pp] = (1.f - m) * cp_ + m * cnew;
                }
                *(float2*)(out_h + ((size_t)b * TT + t) * HH + ch0) = make_float2(hn[0], hn[1]);
                *(float2*)(out_c + ((size_t)b * TT + t) * HH + ch0) = make_float2(cn[0], cn[1]);
                *(float2*)&g_cst[(size_t)b * HH + ch0] = make_float2(cn[0], cn[1]);
                *(float2*)&g_hp[(size_t)(ch0 >> 1) * 64 + b * 2] = make_float2(hn[0], hn[1]);
            }
        }
        gbar(bid, tid, base + (unsigned)(2 * t + 2));
    }

    if (bid == 0 && tid == 0)
        *(volatile unsigned*)&g_epoch = base + (unsigned)(2 * TT);
}

// ---------------- host launcher ----------------
extern "C" void kernel_launch(void* const* d_in, const int* in_sizes, int n_in,
                              void* d_out, int out_size) {
    (void)in_sizes; (void)n_in; (void)out_size;
    const float* X    = (const float*)d_in[0];
    const float* ctx  = (const float*)d_in[1];
    const float* mask = (const float*)d_in[2];
    const int*   cm   = (const int*)d_in[3];
    const float* W[4]; const float* U[4]; const float* C[4]; const float* bi[4];
    for (int gg = 0; gg < 4; gg++) {
        W[gg]  = (const float*)d_in[4 + 4 * gg];
        U[gg]  = (const float*)d_in[5 + 4 * gg];
        C[gg]  = (const float*)d_in[6 + 4 * gg];
        bi[gg] = (const float*)d_in[7 + 4 * gg];
    }
    const float* attW1c = (const float*)d_in[20];
    const float* attW1h = (const float*)d_in[21];
    const float* attB1  = (const float*)d_in[22];
    const float* attW2  = (const float*)d_in[23];
    const float* attB2  = (const float*)d_in[24];
    float* out = (float*)d_out;

    float *xg_ptr = nullptr, *ctr_ptr = nullptr, *ctxC_ptr = nullptr, *zb_ptr = nullptr;
    cudaGetSymbolAddress((void**)&xg_ptr, g_xg);
    cudaGetSymbolAddress((void**)&ctr_ptr, g_ctr);
    cudaGetSymbolAddress((void**)&ctxC_ptr, g_ctxC);
    cudaGetSymbolAddress((void**)&zb_ptr, g_zbias);

    // xg = X@W + b : rows (t*32+b), cols 2048
    dim3 grid1(NCOL / 64, (TT * BB) / 64);
    gemm_proj<<<grid1, 256>>>(X, W[0], W[1], W[2], W[3],
                              bi[0], bi[1], bi[2], bi[3],
                              xg_ptr, NCOL, 512, 512, 1);
    // ctx_trans
    dim3 grid2(AA / 64, (BB * LL) / 64);
    gemm_proj<<<grid2, 256>>>(ctx, attW1c, attW1c, attW1c, attW1c,
                              attB1, attB1, attB1, attB1,
                              ctr_ptr, AA, AA, AA, 0);
    // ctxC = context@C
    dim3 grid3(NCOL / 64, (BB * LL) / 64);
    gemm_proj<<<grid3, 256>>>(ctx, C[0], C[1], C[2], C[3],
                              zb_ptr, zb_ptr, zb_ptr, zb_ptr,
                              ctxC_ptr, NCOL, 512, 512, 0);

    size_t smem_bytes = (size_t)SMEM_FLOATS * sizeof(float);
    static bool attr_set = false;
    if (!attr_set) {
        cudaFuncSetAttribute(recur_kernel, cudaFuncAttributeMaxDynamicSharedMemorySize,
                             (int)smem_bytes);
        attr_set = true;
    }
    recur_kernel<<<NBLK, NTH, smem_bytes>>>(ctx, mask, cm,
                                            U[0], U[1], U[2], U[3], attW1h,
                                            attW2, attB2, out);
}

// round 8
// speedup vs baseline: 1.0944x; 1.0944x over previous
#include <cuda_runtime.h>
#include <cstdint>
#include <cstddef>

#define BB 32
#define TT 128
#define LL 64
#define HH 512
#define AA 256
#define DD 512
#define NCOL 2048
#define UCOLS 2304
#define NBLK 144
#define NTH 512
#define QCH 128

typedef unsigned long long u64;

// ---------------- device scratch ----------------
__device__ float g_xg[(size_t)TT * BB * NCOL];     // [t*32+b][col]
__device__ float g_ctr[(size_t)BB * LL * AA];      // ctx_trans [b*64+l][a]
__device__ float g_ctxC[(size_t)BB * LL * NCOL];   // context@C [b*64+l][col]
__device__ float g_gbuf[(size_t)BB * NCOL];        // [b][col]
__device__ float g_attv[(size_t)BB * AA];          // [b][a]
__device__ float g_hp[(size_t)256 * BB * 2];       // h pairs [k2][b]{e,o}
__device__ float g_cst[(size_t)BB * HH];           // c state [b][ch]
__device__ float g_zbias[512];
__device__ unsigned g_arr[NBLK * 32];              // arrival flags, 128B apart
__device__ unsigned g_epoch;

// ---------------- helpers ----------------
__device__ __forceinline__ u64 pk2(float lo, float hi) {
    u64 r; asm("mov.b64 %0, {%1,%2};" : "=l"(r) : "f"(lo), "f"(hi)); return r;
}
__device__ __forceinline__ float2 upk2(u64 v) {
    float2 r; asm("mov.b64 {%0,%1}, %2;" : "=f"(r.x), "=f"(r.y) : "l"(v)); return r;
}
__device__ __forceinline__ u64 fma2(u64 a, u64 b, u64 c) {
    u64 d; asm("fma.rn.f32x2 %0, %1, %2, %3;" : "=l"(d) : "l"(a), "l"(b), "l"(c)); return d;
}
__device__ __forceinline__ u64 add2(u64 a, u64 b) {
    u64 d; asm("add.rn.f32x2 %0, %1, %2;" : "=l"(d) : "l"(a), "l"(b)); return d;
}
__device__ __forceinline__ float tanh_ap(float x) {
    float y; asm("tanh.approx.f32 %0, %1;" : "=f"(y) : "f"(x)); return y;
}
__device__ __forceinline__ float sig_ap(float x) {
    return fmaf(tanh_ap(0.5f * x), 0.5f, 0.5f);
}

// flat grid barrier: every block polls all arrival flags (no release hop).
// trailing __threadfence() is load-bearing: fence.gpu -> CCTL.IVALL (L1 flush)
// so post-barrier global reads see other SMs' writes.
__device__ __forceinline__ void gbar(int bid, int tid, unsigned gen) {
    __syncthreads();
    if (tid == 0) {
        __threadfence();
        *(volatile unsigned*)&g_arr[bid * 32] = gen;
    }
    if (tid < NBLK) {
        while (*(volatile unsigned*)&g_arr[tid * 32] < gen) { }
    }
    __syncthreads();
    if (tid == 0) __threadfence();
    __syncthreads();
}

// ---------------- prologue GEMM, f32x2 inner product ----------------
__global__ void __launch_bounds__(256) gemm_proj(
    const float* __restrict__ A,
    const float* __restrict__ Wa, const float* __restrict__ Wb,
    const float* __restrict__ Wc, const float* __restrict__ Wd,
    const float* __restrict__ ba, const float* __restrict__ bbi,
    const float* __restrict__ bc, const float* __restrict__ bd,
    float* __restrict__ Out, int Ncols, int wN, int wstride, int tb_mode)
{
    __shared__ u64 As2[8][64];
    __shared__ u64 Bs2[8][64];
    int tid = threadIdx.x;
    int ntile = blockIdx.x, mtile = blockIdx.y;

    int gate = (ntile * 64) / 512;
    const float* Wsel = (gate == 0) ? Wa : (gate == 1) ? Wb : (gate == 2) ? Wc : Wd;
    const float* bsel = (gate == 0) ? ba : (gate == 1) ? bbi : (gate == 2) ? bc : bd;
    int ncolbase = (ntile * 64) % wN;

    int a_r = tid >> 2;
    int a_k = (tid & 3) * 4;
    int grow = mtile * 64 + a_r;
    const float* aptr;
    if (tb_mode) {
        int t = grow >> 5, b = grow & 31;
        aptr = A + ((size_t)(b * TT + t)) * DD;
    } else {
        aptr = A + (size_t)grow * DD;
    }
    int bl_k2 = (tid >> 4) & 7;
    int bl_n  = (tid & 15) * 4;
    bool bldr = tid < 128;

    int tx = tid & 15, ty = tid >> 4;
    u64 acc2[4][4];
#pragma unroll
    for (int i = 0; i < 4; i++)
#pragma unroll
        for (int j = 0; j < 4; j++) acc2[i][j] = 0;

    for (int k0 = 0; k0 < DD; k0 += 16) {
        float4 av = *(const float4*)(aptr + k0 + a_k);
        float4 b0, b1;
        if (bldr) {
            b0 = *(const float4*)(Wsel + (size_t)(k0 + 2 * bl_k2) * wstride + ncolbase + bl_n);
            b1 = *(const float4*)(Wsel + (size_t)(k0 + 2 * bl_k2 + 1) * wstride + ncolbase + bl_n);
        }
        __syncthreads();
        As2[(a_k >> 1)][a_r]     = pk2(av.x, av.y);
        As2[(a_k >> 1) + 1][a_r] = pk2(av.z, av.w);
        if (bldr) {
            Bs2[bl_k2][bl_n + 0] = pk2(b0.x, b1.x);
            Bs2[bl_k2][bl_n + 1] = pk2(b0.y, b1.y);
            Bs2[bl_k2][bl_n + 2] = pk2(b0.z, b1.z);
            Bs2[bl_k2][bl_n + 3] = pk2(b0.w, b1.w);
        }
        __syncthreads();
#pragma unroll
        for (int k2 = 0; k2 < 8; k2++) {
            ulonglong2 a01 = *(const ulonglong2*)&As2[k2][ty * 4];
            ulonglong2 a23 = *(const ulonglong2*)&As2[k2][ty * 4 + 2];
            ulonglong2 b01 = *(const ulonglong2*)&Bs2[k2][tx * 4];
            ulonglong2 b23 = *(const ulonglong2*)&Bs2[k2][tx * 4 + 2];
            u64 aa[4] = {a01.x, a01.y, a23.x, a23.y};
            u64 bb4[4] = {b01.x, b01.y, b23.x, b23.y};
#pragma unroll
            for (int i = 0; i < 4; i++)
#pragma unroll
                for (int j = 0; j < 4; j++) acc2[i][j] = fma2(aa[i], bb4[j], acc2[i][j]);
        }
    }
#pragma unroll
    for (int i = 0; i < 4; i++) {
        int gr = mtile * 64 + ty * 4 + i;
        float r[4];
#pragma unroll
        for (int j = 0; j < 4; j++) {
            float2 v = upk2(acc2[i][j]);
            r[j] = v.x + v.y + bsel[(ncolbase + tx * 4 + j) % wN];
        }
        *(float4*)(Out + (size_t)gr * Ncols + ntile * 64 + tx * 4) =
            make_float4(r[0], r[1], r[2], r[3]);
    }
}

// smem map (floats):
//   sW   [0, 8192)        : 4096 u64 = persistent weight slice [k2][16 cols]
//   sTp  [8192, 24576)    : 8192 u64 = h pairs [k2][32 b]
//   sRed [24576, 26624)   : P1 k-partials (4x512); P2 out_x partials + sRedU
//   aux  [26624, 27912)
#define OFF_TP    8192
#define OFF_RED   24576
#define OFF_ATT   26624
#define OFF_W2    26880
#define OFF_E     27136
#define OFF_A     27200
#define OFF_APAIR 27264
#define OFF_G     27392
#define OFF_SUM   27904
#define SMEM_FLOATS 27912

// ---------------- persistent recurrent kernel ----------------
__global__ void __launch_bounds__(NTH, 1) recur_kernel(
    const float* __restrict__ context,
    const float* __restrict__ mask,
    const int*   __restrict__ cmask,
    const float* __restrict__ U0, const float* __restrict__ U1,
    const float* __restrict__ U2, const float* __restrict__ U3,
    const float* __restrict__ W1h,
    const float* __restrict__ W2, const float* __restrict__ b2,
    float* __restrict__ out)
{
    extern __shared__ float smem[];
    u64*   sW64  = (u64*)smem;
    float* sTp   = smem + OFF_TP;
    u64*   sTp64 = (u64*)sTp;
    float* sRed  = smem + OFF_RED;
    u64*   sRedU = (u64*)(sRed + 1536);   // 256 u64
    float* sAtt  = smem + OFF_ATT;
    float* sW2s  = smem + OFF_W2;
    float* sE    = smem + OFF_E;
    float* sA    = smem + OFF_A;
    u64*   sApr  = (u64*)(smem + OFF_APAIR);
    float* sG    = smem + OFF_G;
    float* sSum  = smem + OFF_SUM;

    const int tid = threadIdx.x;
    const int bid = blockIdx.x;
    float* out_h = out;
    float* out_c = out + (size_t)BB * TT * HH;
    float* out_x = out + (size_t)2 * BB * TT * HH;
    const float b2v = b2[0];

    unsigned base = *(volatile unsigned*)&g_epoch;

    // P1 roles: thread = colL(16) x bq(8) x kq(4)
    const int c0   = bid * 16;
    const int colL = tid & 15;
    const int bq   = (tid >> 4) & 7;
    const int kq   = tid >> 7;

    // ---- startup: persistent weight slice into SMEM ----
    {
        const float* Wsrc;
        int wn, cbase;
        if (bid < 128) {
            int gate = c0 >> 9;
            Wsrc = (gate == 0) ? U0 : (gate == 1) ? U1 : (gate == 2) ? U2 : U3;
            wn = 512; cbase = c0 & 511;
        } else {
            Wsrc = W1h; wn = 256; cbase = c0 - 2048;
        }
        for (int i = tid; i < 4096; i += NTH) {
            int k2 = i >> 4, cl = i & 15;
            int ch = cbase + cl;
            float e = Wsrc[(size_t)(2 * k2) * wn + ch];
            float o = Wsrc[(size_t)(2 * k2 + 1) * wn + ch];
            sW64[k2 * 16 + cl] = pk2(e, o);
        }
    }

    // P2 roles
    const bool p2act = (bid < 128);
    const int pb = bid >> 2;
    const int pq = bid & 3;
    const int chp = tid & 255;         // local col-pair (512 local cols)
    const int lh  = tid >> 8;          // l-half

    // ---- startup: register-resident ctxC slice for P2 ----
    u64 rv[32];
    {
        int lc0 = chp * 2;
        int gg = lc0 >> 7, ii = lc0 & 127;
        int gcol = gg * 512 + pq * QCH + ii;
        const float* cc = g_ctxC + ((size_t)(pb * 64 + lh * 32)) * NCOL + gcol;
        if (p2act) {
#pragma unroll
            for (int li = 0; li < 32; li++)
                rv[li] = *(const u64*)(cc + (size_t)li * NCOL);
        } else {
#pragma unroll
            for (int li = 0; li < 32; li++) rv[li] = 0;
        }
    }
    if (tid < AA) sW2s[tid] = W2[tid];

    for (int t = 0; t < TT; t++) {
        // ================= PHASE 1: unified GEMM over h =================
        if (t > 0) {
            const float4* src = (const float4*)g_hp;
            float4* dst = (float4*)sTp;
            for (int f4 = tid; f4 < 4096; f4 += NTH) dst[f4] = src[f4];
        }
        __syncthreads();

        u64 ac[4] = {0, 0, 0, 0};
        if (t > 0) {
            const u64* wp = sW64 + (kq * 64) * 16 + colL;
            const u64* hp = sTp64 + (kq * 64) * 32 + bq * 4;
#pragma unroll 8
            for (int p = 0; p < 64; p++) {
                u64 w = *wp;
                ulonglong2 ha = *(const ulonglong2*)hp;
                ulonglong2 hb = *(const ulonglong2*)(hp + 2);
                ac[0] = fma2(w, ha.x, ac[0]);
                ac[1] = fma2(w, ha.y, ac[1]);
                ac[2] = fma2(w, hb.x, ac[2]);
                ac[3] = fma2(w, hb.y, ac[3]);
                wp += 16; hp += 32;
            }
        }
#pragma unroll
        for (int bi = 0; bi < 4; bi++) {
            float2 r = upk2(ac[bi]);
            sRed[kq * 512 + (bq * 4 + bi) * 16 + colL] = r.x + r.y;
        }
        __syncthreads();
        {
            int o = tid;
            float s = sRed[o] + sRed[512 + o] + sRed[1024 + o] + sRed[1536 + o];
            int b = o >> 4, cl = o & 15;
            if (bid < 128) {
                int col = c0 + cl;
                s += g_xg[((size_t)t * BB + b) * NCOL + col];
                g_gbuf[(size_t)b * NCOL + col] = s;
            } else {
                g_attv[b * AA + (c0 - 2048) + cl] = s;
            }
        }
        gbar(bid, tid, base + (unsigned)(2 * t + 1));

        // ================= PHASE 2: per (b, quarter) block =================
        if (p2act) {
            const int b = pb;
            if (tid < AA) sAtt[tid] = g_attv[b * AA + tid];
            __syncthreads();
            // scores: warp per 4 l
            {
                int warp = tid >> 5, lane = tid & 31;
#pragma unroll
                for (int i = 0; i < 4; i++) {
                    int l = warp * 4 + i;
                    const float* ct = g_ctr + ((size_t)b * LL + l) * AA;
                    float p = 0.f;
#pragma unroll
                    for (int j = 0; j < 8; j++) {
                        int a = lane + j * 32;
                        p += tanh_ap(ct[a] + sAtt[a]) * sW2s[a];
                    }
#pragma unroll
                    for (int o = 16; o > 0; o >>= 1) p += __shfl_xor_sync(0xffffffffu, p, o);
                    if (lane == 0)
                        sE[l] = __expf(p + b2v) * (float)cmask[b * LL + l];
                }
            }
            __syncthreads();
            if (tid < 32) {
                float v = sE[tid] + sE[tid + 32];
#pragma unroll
                for (int o = 16; o > 0; o >>= 1) v += __shfl_xor_sync(0xffffffffu, v, o);
                if (tid == 0) sSum[0] = v;
            }
            __syncthreads();
            if (tid < 64) {
                float av = sE[tid] * __fdividef(1.0f, sSum[0]);
                sA[tid] = av;
                sApr[tid] = pk2(av, av);
            }
            __syncthreads();

            // gsum from registers (32 fma2)
            u64 acc = 0;
#pragma unroll
            for (int li = 0; li < 32; li++)
                acc = fma2(rv[li], sApr[lh * 32 + li], acc);
            if (lh == 1) sRedU[chp] = acc;

            // out_x partials
            if (tid < 256) {
                int lg = tid >> 5, d4 = tid & 31;
                float4 xp = make_float4(0.f, 0.f, 0.f, 0.f);
                const float* cb = context + ((size_t)b * LL + lg * 8) * DD + pq * QCH + d4 * 4;
#pragma unroll
                for (int li = 0; li < 8; li++) {
                    float av = sA[lg * 8 + li];
                    float4 v = *(const float4*)(cb + (size_t)li * DD);
                    xp.x += av * v.x; xp.y += av * v.y; xp.z += av * v.z; xp.w += av * v.w;
                }
                *(float4*)&sRed[tid * 4] = xp;
            }
            __syncthreads();
            if (lh == 0) {
                u64 tot = add2(acc, sRedU[chp]);
                *(u64*)&sG[chp * 2] = tot;
            }
            if (tid < 32) {
                float4 s = make_float4(0.f, 0.f, 0.f, 0.f);
#pragma unroll
                for (int lg = 0; lg < 8; lg++) {
                    float4 v = *(const float4*)&sRed[(lg * 32 + tid) * 4];
                    s.x += v.x; s.y += v.y; s.z += v.z; s.w += v.w;
                }
                *(float4*)(out_x + ((size_t)b * TT + t) * DD + pq * QCH + tid * 4) = s;
            }
            __syncthreads();

            // fused LSTM epilogue: 64 ch-pairs
            if (tid < 64) {
                int i2 = tid;
                int ch0 = pq * QCH + i2 * 2;
                float gs[4][2];
#pragma unroll
                for (int g = 0; g < 4; g++) {
                    float2 sg = *(const float2*)&sG[(g * 64 + i2) * 2];
                    float2 gb = *(const float2*)&g_gbuf[(size_t)b * NCOL + g * 512 + ch0];
                    gs[g][0] = sg.x + gb.x;
                    gs[g][1] = sg.y + gb.y;
                }
                float2 cprev = make_float2(0.f, 0.f), hprev = make_float2(0.f, 0.f);
                if (t > 0) {
                    cprev = *(const float2*)&g_cst[(size_t)b * HH + ch0];
                    hprev = *(const float2*)&g_hp[(size_t)(ch0 >> 1) * 64 + b * 2];
                }
                float m = mask[b * TT + t];
                float hn[2], cn[2];
#pragma unroll
                for (int pp = 0; pp < 2; pp++) {
                    float iv = sig_ap(gs[0][pp]);
                    float fv = sig_ap(gs[1][pp]);
                    float gv = tanh_ap(gs[2][pp]);
                    float ov = sig_ap(gs[3][pp]);
                    float cp_ = pp ? cprev.y : cprev.x;
                    float hp_ = pp ? hprev.y : hprev.x;
                    float cnew = fv * cp_ + iv * gv;
                    float hnew = ov * tanh_ap(cnew);
                    hn[pp] = (1.f - m) * hp_ + m * hnew;
                    cn[pp] = (1.f - m) * cp_ + m * cnew;
                }
                *(float2*)(out_h + ((size_t)b * TT + t) * HH + ch0) = make_float2(hn[0], hn[1]);
                *(float2*)(out_c + ((size_t)b * TT + t) * HH + ch0) = make_float2(cn[0], cn[1]);
                *(float2*)&g_cst[(size_t)b * HH + ch0] = make_float2(cn[0], cn[1]);
                *(float2*)&g_hp[(size_t)(ch0 >> 1) * 64 + b * 2] = make_float2(hn[0], hn[1]);
            }
        }
        gbar(bid, tid, base + (unsigned)(2 * t + 2));
    }

    if (bid == 0 && tid == 0)
        *(volatile unsigned*)&g_epoch = base + (unsigned)(2 * TT);
}

// ---------------- host launcher ----------------
extern "C" void kernel_launch(void* const* d_in, const int* in_sizes, int n_in,
                              void* d_out, int out_size) {
    (void)in_sizes; (void)n_in; (void)out_size;
    const float* X    = (const float*)d_in[0];
    const float* ctx  = (const float*)d_in[1];
    const float* mask = (const float*)d_in[2];
    const int*   cm   = (const int*)d_in[3];
    const float* W[4]; const float* U[4]; const float* C[4]; const float* bi[4];
    for (int gg = 0; gg < 4; gg++) {
        W[gg]  = (const float*)d_in[4 + 4 * gg];
        U[gg]  = (const float*)d_in[5 + 4 * gg];
        C[gg]  = (const float*)d_in[6 + 4 * gg];
        bi[gg] = (const float*)d_in[7 + 4 * gg];
    }
    const float* attW1c = (const float*)d_in[20];
    const float* attW1h = (const float*)d_in[21];
    const float* attB1  = (const float*)d_in[22];
    const float* attW2  = (const float*)d_in[23];
    const float* attB2  = (const float*)d_in[24];
    float* out = (float*)d_out;

    float *xg_ptr = nullptr, *ctr_ptr = nullptr, *ctxC_ptr = nullptr, *zb_ptr = nullptr;
    cudaGetSymbolAddress((void**)&xg_ptr, g_xg);
    cudaGetSymbolAddress((void**)&ctr_ptr, g_ctr);
    cudaGetSymbolAddress((void**)&ctxC_ptr, g_ctxC);
    cudaGetSymbolAddress((void**)&zb_ptr, g_zbias);

    // xg = X@W + b : rows (t*32+b), cols 2048
    dim3 grid1(NCOL / 64, (TT * BB) / 64);
    gemm_proj<<<grid1, 256>>>(X, W[0], W[1], W[2], W[3],
                              bi[0], bi[1], bi[2], bi[3],
                              xg_ptr, NCOL, 512, 512, 1);
    // ctx_trans
    dim3 grid2(AA / 64, (BB * LL) / 64);
    gemm_proj<<<grid2, 256>>>(ctx, attW1c, attW1c, attW1c, attW1c,
                              attB1, attB1, attB1, attB1,
                              ctr_ptr, AA, AA, AA, 0);
    // ctxC = context@C
    dim3 grid3(NCOL / 64, (BB * LL) / 64);
    gemm_proj<<<grid3, 256>>>(ctx, C[0], C[1], C[2], C[3],
                              zb_ptr, zb_ptr, zb_ptr, zb_ptr,
                              ctxC_ptr, NCOL, 512, 512, 0);

    size_t smem_bytes = (size_t)SMEM_FLOATS * sizeof(float);
    static bool attr_set = false;
    if (!attr_set) {
        cudaFuncSetAttribute(recur_kernel, cudaFuncAttributeMaxDynamicSharedMemorySize,
                             (int)smem_bytes);
        attr_set = true;
    }
    recur_kernel<<<NBLK, NTH, smem_bytes>>>(ctx, mask, cm,
                                            U[0], U[1], U[2], U[3], attW1h,
                                            attW2, attB2, out);
}